// round 12
// baseline (speedup 1.0000x reference)
#include <cuda_runtime.h>
#include <math_constants.h>
#include <cstdint>

#define D_MODEL  1024
#define ALPHA    0.5f
#define WINDOW   64          // 0.5^64 ~ 5e-20: truncation far below 1e-3 rel-err
#define CHUNK    1024        // tokens per consumer chunk
#define ROWS_PER_BLOCK 8     // producer: 8 warps/block, 1 row each

#define MAX_TOKENS 262144
#define MAX_CHUNKS (MAX_TOKENS / CHUNK)     // 256

// Device globals (no allocation at launch). Zero-initialized at module load;
// the observer-reset protocol restores counters to zero before kernel exit,
// so every graph replay starts from identical state.
__device__ float g_scores[MAX_TOKENS];
__device__ int   g_count[MAX_CHUNKS];   // rows produced per chunk
__device__ int   g_obs[MAX_CHUNKS];     // consumers done per chunk

// Release/acquire without MEMBAR/CCTL: ordering carried by the atomic at L2.
__device__ __forceinline__ void red_release_add1(int* addr)
{
    asm volatile("red.release.gpu.global.add.s32 [%0], 1;" :: "l"(addr) : "memory");
}
__device__ __forceinline__ int ld_acquire(const int* addr)
{
    int v;
    asm volatile("ld.acquire.gpu.global.s32 %0, [%1];" : "=r"(v) : "l"(addr) : "memory");
    return v;
}

__device__ __forceinline__ void atomic_max_float(float* addr, float val)
{
    // Global max is known-positive (~2.9); 0xAA poison is a tiny negative
    // float whose signed-int rep loses to any positive posting.
    if (val >= 0.f)
        atomicMax(reinterpret_cast<int*>(addr), __float_as_int(val));
    else
        atomicMin(reinterpret_cast<unsigned int*>(addr), __float_as_uint(val));
}

// ---------------------------------------------------------------------------
// Single kernel, two block roles.
//   bid < nprod : PRODUCER — exact R9 score body (7.33 TB/s structure).
//                 Only change: lane0's score store is followed by one
//                 red.release on the chunk counter (replaces __threadfence,
//                 which emitted CCTL.IVALL and cost 12 us in R10).
//   bid >= nprod: CONSUMER — trailing 256 blocks (scheduled last). Spin via
//                 ld.acquire until chunk e and halo chunk e-1 are complete,
//                 then windowed EMA + block max + atomicMax, then the
//                 self-cleaning counter reset.
// ---------------------------------------------------------------------------
__global__ __launch_bounds__(256)
void ema_probe_kernel(const float* __restrict__ x,
                      const float* __restrict__ W,
                      const float* __restrict__ b,
                      float* __restrict__ out,
                      int n, int nprod)
{
    __shared__ float s[CHUNK + WINDOW];
    __shared__ float wmax[8];

    const int tid  = threadIdx.x;
    const int warp = tid >> 5;
    const int lane = tid & 31;
    const int bid  = blockIdx.x;

    if (bid < nprod) {
        // ================= PRODUCER (frozen R9 body) =================
        if (bid == 0 && tid == 0)
            *out = -CUDART_INF_F;

        const int row = bid * ROWS_PER_BLOCK + warp;
        if (row < n) {
            float4 w[8];
            const float4* W4 = reinterpret_cast<const float4*>(W);
            #pragma unroll
            for (int i = 0; i < 8; i++)
                w[i] = __ldg(&W4[lane + i * 32]);

            const float4* xr =
                reinterpret_cast<const float4*>(x + (size_t)row * D_MODEL);

            float4 xv[8];
            #pragma unroll
            for (int i = 0; i < 8; i++)              // 8 front-batched LDG.128
                xv[i] = __ldcs(&xr[lane + i * 32]);

            float acc = 0.f;
            #pragma unroll
            for (int i = 0; i < 8; i++) {
                acc = fmaf(xv[i].x, w[i].x, acc);
                acc = fmaf(xv[i].y, w[i].y, acc);
                acc = fmaf(xv[i].z, w[i].z, acc);
                acc = fmaf(xv[i].w, w[i].w, acc);
            }
            #pragma unroll
            for (int o = 16; o; o >>= 1)
                acc += __shfl_xor_sync(0xffffffffu, acc, o);

            if (lane == 0) {
                g_scores[row] = acc + __ldg(b);
                red_release_add1(&g_count[row / CHUNK]);   // no MEMBAR/CCTL
            }
        }
        return;
    }

    // ================= CONSUMER =================
    const int nchunk = (n + CHUNK - 1) / CHUNK;
    const int e      = bid - nprod;
    if (e >= nchunk) return;
    const int base = e * CHUNK;

    const int tgt_e = min(CHUNK, n - base);          // rows in chunk e (=1024)
    if (tid == 0) {
        while (ld_acquire(&g_count[e]) < tgt_e)
            __nanosleep(64);
        if (e > 0)
            while (ld_acquire(&g_count[e - 1]) < CHUNK)
                __nanosleep(64);
    }
    __syncthreads();

    // Load halo + chunk as float4 (272 vectors); base-WINDOW is 4-aligned.
    // __ldcg: bypass L1 (data freshly written via L2 by other SMs).
    #pragma unroll
    for (int i = tid; i < (CHUNK + WINDOW) / 4; i += 256) {
        const int g4 = (base - WINDOW) / 4 + i;
        const int g0 = g4 * 4;
        float4 v;
        if (g0 >= 0 && g0 + 3 < n) {
            v = __ldcg(&reinterpret_cast<const float4*>(g_scores)[g4]);
        } else {
            v.x = (g0 + 0 >= 0 && g0 + 0 < n) ? __ldcg(&g_scores[g0 + 0]) : 0.f;
            v.y = (g0 + 1 >= 0 && g0 + 1 < n) ? __ldcg(&g_scores[g0 + 1]) : 0.f;
            v.z = (g0 + 2 >= 0 && g0 + 2 < n) ? __ldcg(&g_scores[g0 + 2]) : 0.f;
            v.w = (g0 + 3 >= 0 && g0 + 3 < n) ? __ldcg(&g_scores[g0 + 3]) : 0.f;
        }
        *reinterpret_cast<float4*>(&s[i * 4]) = v;
    }
    __syncthreads();

    // Windowed EMA: thread handles 4 consecutive tokens starting at p.
    // Seed via 4 independent 16-FMA chains (exact: group weight 0.5^16).
    const int p = tid * 4;
    float a0 = 0.f, a1 = 0.f, a2 = 0.f, a3 = 0.f, wc = ALPHA;
    #pragma unroll
    for (int k = 0; k < 16; k++) {
        a0 = fmaf(wc, s[WINDOW + p - k],      a0);
        a1 = fmaf(wc, s[WINDOW + p - 16 - k], a1);
        a2 = fmaf(wc, s[WINDOW + p - 32 - k], a2);
        a3 = fmaf(wc, s[WINDOW + p - 48 - k], a3);
        wc *= (1.0f - ALPHA);
    }
    const float c16 = 1.0f / 65536.0f;               // 0.5^16
    float eacc = fmaf(c16, fmaf(c16, fmaf(c16, a3, a2), a1), a0);
    float m = (base + p < n) ? eacc : -CUDART_INF_F;

    #pragma unroll
    for (int j = 1; j < 4; j++) {                    // exact recurrence
        eacc = fmaf(ALPHA, s[WINDOW + p + j], (1.0f - ALPHA) * eacc);
        if (base + p + j < n) m = fmaxf(m, eacc);
    }

    // Block max + one global atomic per block
    #pragma unroll
    for (int o = 16; o; o >>= 1)
        m = fmaxf(m, __shfl_xor_sync(0xffffffffu, m, o));
    if (lane == 0) wmax[warp] = m;
    __syncthreads();
    if (tid < 8) {
        float r = wmax[tid];
        #pragma unroll
        for (int o = 4; o; o >>= 1)
            r = fmaxf(r, __shfl_xor_sync(0xffu, r, o));
        if (tid == 0)
            atomic_max_float(out, r);
    }

    // Self-cleaning reset (graph-replay safe): chunk c is observed by
    // consumers c and c+1 (2 observers; last chunk: 1). The FINAL observer —
    // which has passed its waits and finished reading — resets both words.
    __syncthreads();
    if (tid == 0) {
        int t = (e == nchunk - 1) ? 1 : 2;
        if (atomicAdd(&g_obs[e], 1) + 1 == t) {
            atomicExch(&g_count[e], 0);
            atomicExch(&g_obs[e], 0);
        }
        if (e > 0) {
            if (atomicAdd(&g_obs[e - 1], 1) + 1 == 2) {
                atomicExch(&g_count[e - 1], 0);
                atomicExch(&g_obs[e - 1], 0);
            }
        }
    }
}

// ---------------------------------------------------------------------------
extern "C" void kernel_launch(void* const* d_in, const int* in_sizes, int n_in,
                              void* d_out, int out_size)
{
    const float* x = (const float*)d_in[0];
    const float* W = (const float*)d_in[1];
    const float* b = (const float*)d_in[2];
    float* out     = (float*)d_out;

    const int n = in_sizes[0] / D_MODEL;                       // 262144
    const int nprod  = (n + ROWS_PER_BLOCK - 1) / ROWS_PER_BLOCK;  // 32768
    const int nchunk = (n + CHUNK - 1) / CHUNK;                // 256

    ema_probe_kernel<<<nprod + nchunk, 256>>>(x, W, b, out, n, nprod);
}

// round 15
// speedup vs baseline: 1.8575x; 1.8575x over previous
#include <cuda_runtime.h>
#include <math_constants.h>
#include <cstdint>

#define D_MODEL  1024
#define ALPHA    0.5f
#define WINDOW   64          // 0.5^64 ~ 5e-20: truncation far below 1e-3 rel-err

// Scratch for per-token scores (1 MB). Device global: no allocation at launch.
#define MAX_TOKENS 262144
__device__ float g_scores[MAX_TOKENS];

// -------------------------------------------------------------------------
// Kernel 1: scores[row] = dot(x[row, :], W) + b   (memory-bound, ~1 GB read)
// FROZEN R9 body (7.33 TB/s). One warp per row, single pass, 8 front-batched
// streaming LDG.128, W in registers, PDL trigger. DO NOT ADD ANYTHING:
// fences / release atomics here cost 12-127 us (R10/R12 evidence).
// -------------------------------------------------------------------------
__global__ __launch_bounds__(256)
void score_kernel(const float* __restrict__ x,
                  const float* __restrict__ W,
                  const float* __restrict__ b,
                  float* __restrict__ out,
                  int n_rows)
{
    const int tid  = threadIdx.x;
    const int warp = tid >> 5;
    const int lane = tid & 31;

    // Initialize output to -inf (d_out is poisoned to 0xAA before timing)
    if (blockIdx.x == 0 && tid == 0)
        *out = -CUDART_INF_F;

    const int row = blockIdx.x * 8 + warp;       // 8 warps/block, 1 row each
    if (row < n_rows) {
        // W into registers: lane covers columns {lane*4 + i*128 .. +3}, i=0..7.
        float4 w[8];
        const float4* W4 = reinterpret_cast<const float4*>(W);
        #pragma unroll
        for (int i = 0; i < 8; i++)
            w[i] = __ldg(&W4[lane + i * 32]);

        const float4* xr = reinterpret_cast<const float4*>(x + (size_t)row * D_MODEL);

        // Front-batch 8 independent streaming LDG.128 (MLP=8/thread)
        float4 xv[8];
        #pragma unroll
        for (int i = 0; i < 8; i++)
            xv[i] = __ldcs(&xr[lane + i * 32]);

        float acc = 0.f;
        #pragma unroll
        for (int i = 0; i < 8; i++) {
            acc = fmaf(xv[i].x, w[i].x, acc);
            acc = fmaf(xv[i].y, w[i].y, acc);
            acc = fmaf(xv[i].z, w[i].z, acc);
            acc = fmaf(xv[i].w, w[i].w, acc);
        }
        #pragma unroll
        for (int o = 16; o; o >>= 1)
            acc += __shfl_xor_sync(0xffffffffu, acc, o);

        if (lane == 0)
            g_scores[row] = acc + __ldg(b);
    }

#if __CUDA_ARCH__ >= 900
    // All threads reach this (no early return above): required for PDL.
    cudaTriggerProgrammaticLaunchCompletion();
#endif
}

// -------------------------------------------------------------------------
// Kernel 2: windowed EMA + global max (PDL secondary), smem-free.
// Each thread owns 4 consecutive tokens and loads its full 68-float window
// into REGISTERS via 17 independent float4 loads (one latency round trip,
// no smem staging, no syncthreads on the load path). Seed via 4 independent
// 16-FMA chains combined with 0.5^16 (exact), then 3 recurrence steps.
// -------------------------------------------------------------------------
__device__ __forceinline__ void atomic_max_float(float* addr, float val)
{
    if (val >= 0.f)
        atomicMax(reinterpret_cast<int*>(addr), __float_as_int(val));
    else
        atomicMin(reinterpret_cast<unsigned int*>(addr), __float_as_uint(val));
}

__global__ __launch_bounds__(256)
void ema_max_kernel(float* __restrict__ out, int n)
{
    __shared__ float wmax[8];

    const int tid = threadIdx.x;
    const int j   = (blockIdx.x * 256 + tid) * 4;   // this thread's 1st token

#if __CUDA_ARCH__ >= 900
    // Primary grid's stores to g_scores must be visible before we read.
    cudaGridDependencySynchronize();
#endif

    // Register window v[0..67] = s[j-64 .. j+3]; out-of-range -> 0.
    // s0 = j-64 is a multiple of 4, so float4 indexing is exact.
    float v[68];
    const int s0 = j - WINDOW;
    #pragma unroll
    for (int i = 0; i < 17; i++) {                  // 17 independent LDG.128
        const int g0 = s0 + i * 4;
        float4 q;
        if (g0 >= 0 && g0 + 3 < n) {
            q = __ldg(&reinterpret_cast<const float4*>(g_scores)[s0 / 4 + i]);
        } else {
            q.x = (g0 + 0 >= 0 && g0 + 0 < n) ? g_scores[g0 + 0] : 0.f;
            q.y = (g0 + 1 >= 0 && g0 + 1 < n) ? g_scores[g0 + 1] : 0.f;
            q.z = (g0 + 2 >= 0 && g0 + 2 < n) ? g_scores[g0 + 2] : 0.f;
            q.w = (g0 + 3 >= 0 && g0 + 3 < n) ? g_scores[g0 + 3] : 0.f;
        }
        v[i * 4 + 0] = q.x;
        v[i * 4 + 1] = q.y;
        v[i * 4 + 2] = q.z;
        v[i * 4 + 3] = q.w;
    }

    // ema_j = sum_{k=0..63} 0.5^{k+1} v[64-k], as 4 independent 16-FMA chains:
    // chain G sums k=16G..16G+15 -> taps v[64-16G-k'], weight 0.5^{16G} folded in.
    float a0 = 0.f, a1 = 0.f, a2 = 0.f, a3 = 0.f, wc = ALPHA;
    #pragma unroll
    for (int k = 0; k < 16; k++) {
        a0 = fmaf(wc, v[64 - k], a0);
        a1 = fmaf(wc, v[48 - k], a1);
        a2 = fmaf(wc, v[32 - k], a2);
        a3 = fmaf(wc, v[16 - k], a3);
        wc *= (1.0f - ALPHA);
    }
    const float c16 = 1.0f / 65536.0f;              // 0.5^16
    float e = fmaf(c16, fmaf(c16, fmaf(c16, a3, a2), a1), a0);
    float m = (j < n) ? e : -CUDART_INF_F;

    // Exact recurrence for tokens j+1..j+3.
    #pragma unroll
    for (int t = 1; t < 4; t++) {
        e = fmaf(ALPHA, v[64 + t], (1.0f - ALPHA) * e);
        if (j + t < n) m = fmaxf(m, e);
    }

    // Block max + one global atomic per block (256 atomics chip-wide).
    #pragma unroll
    for (int o = 16; o; o >>= 1)
        m = fmaxf(m, __shfl_xor_sync(0xffffffffu, m, o));
    if ((tid & 31) == 0) wmax[tid >> 5] = m;
    __syncthreads();
    if (tid < 8) {
        float r = wmax[tid];
        #pragma unroll
        for (int o = 4; o; o >>= 1)
            r = fmaxf(r, __shfl_xor_sync(0xffu, r, o));
        if (tid == 0)
            atomic_max_float(out, r);
    }
}

// -------------------------------------------------------------------------
extern "C" void kernel_launch(void* const* d_in, const int* in_sizes, int n_in,
                              void* d_out, int out_size)
{
    const float* x = (const float*)d_in[0];
    const float* W = (const float*)d_in[1];
    const float* b = (const float*)d_in[2];
    float* out     = (float*)d_out;

    const int n = in_sizes[0] / D_MODEL;    // 262144

    const int grid1 = (n + 7) / 8;                     // 32768 blocks
    score_kernel<<<grid1, 256>>>(x, W, b, out, n);

    // PDL secondary: launch overlaps primary's tail; kernel synchronizes on
    // the primary grid before touching g_scores.
    const int grid2 = (n + 1023) / 1024;               // 256 blocks
    cudaLaunchConfig_t cfg = {};
    cfg.gridDim  = dim3((unsigned)grid2, 1, 1);
    cfg.blockDim = dim3(256, 1, 1);
    cfg.dynamicSmemBytes = 0;
    cfg.stream = 0;
    cudaLaunchAttribute attrs[1];
    attrs[0].id = cudaLaunchAttributeProgrammaticStreamSerialization;
    attrs[0].val.programmaticStreamSerializationAllowed = 1;
    cfg.attrs = attrs;
    cfg.numAttrs = 1;
    cudaError_t err = cudaLaunchKernelEx(&cfg, ema_max_kernel, out, n);
    if (err != cudaSuccess) {
        // Deterministic fallback (attribute support is fixed per driver).
        ema_max_kernel<<<grid2, 256>>>(out, n);
    }
}